// round 3
// baseline (speedup 1.0000x reference)
#include <cuda_runtime.h>
#include <cuda_bf16.h>
#include <math.h>

// Problem constants (fixed shapes)
constexpr int Bc = 64;    // batch
constexpr int Sc = 512;   // seq
constexpr int Hc = 768;   // hidden
constexpr int Nc = 128;   // nodes
constexpr int Ec = 1024;  // edges per batch
constexpr int GHc = 128;  // gcn hidden
constexpr int FHc = 256;  // fc hidden
constexpr int BNc = Bc * Nc;   // 8192
constexpr int BSc = Bc * Sc;   // 32768
constexpr int NEc = Bc * Ec;   // 65536

// Scratch (device globals — no allocation allowed)
__device__ __align__(16) float g_gate[BSc];
__device__ float g_cnt[BNc];
__device__ float g_deg[BNc];
__device__ float g_dinv[BNc];
__device__ __align__(16) float g_nodef[(size_t)BNc * Hc];   // 24 MiB
__device__ __align__(16) float g_h[(size_t)BNc * GHc];      // 4 MiB
__device__ __align__(16) float g_acc[(size_t)BNc * GHc];    // 4 MiB
__device__ __align__(16) float g_pool[Bc * GHc];

// ---------------------------------------------------------------------------
// 1) gate[b,s] = sigmoid(dot(last_hidden[b,s,:], wr) + br)
//    one warp per row, float4 loads
// ---------------------------------------------------------------------------
__global__ void gate_kernel(const float* __restrict__ lh,
                            const float* __restrict__ wr,
                            const float* __restrict__ brp) {
    int warp = threadIdx.x >> 5, lane = threadIdx.x & 31;
    int row = blockIdx.x * 8 + warp;
    const float4* r4 = (const float4*)(lh + (size_t)row * Hc);
    const float4* w4 = (const float4*)wr;
    float s = 0.f;
#pragma unroll
    for (int j = 0; j < 6; ++j) {           // 6*32*4 = 768
        float4 a = r4[lane + j * 32];
        float4 w = w4[lane + j * 32];
        s += a.x * w.x + a.y * w.y + a.z * w.z + a.w * w.w;
    }
#pragma unroll
    for (int o = 16; o; o >>= 1) s += __shfl_xor_sync(0xffffffffu, s, o);
    if (lane == 0) g_gate[row] = 1.f / (1.f + expf(-(s + brp[0])));
}

// ---------------------------------------------------------------------------
// 2) init counts/deg (deg starts at 1.0 for the self loop)
// ---------------------------------------------------------------------------
__global__ void init_kernel() {
    int i = blockIdx.x * 256 + threadIdx.x;
    if (i < BNc) { g_cnt[i] = 0.f; g_deg[i] = 1.f; }
}

__global__ void cntdeg_kernel(const int* __restrict__ submap,
                              const int* __restrict__ eidx) {
    int i = blockIdx.x * 256 + threadIdx.x;
    if (i < BSc) {
        int b = i >> 9;                              // /512
        atomicAdd(&g_cnt[b * Nc + submap[i]], 1.f);
    } else {
        int e = i - BSc;
        if (e < NEc) {
            int b = e >> 10;                         // /1024
            int le = e & (Ec - 1);
            int dst = eidx[b * 2 * Ec + Ec + le];
            atomicAdd(&g_deg[b * Nc + dst], 1.f);
        }
    }
}

__global__ void dinv_kernel() {
    int i = blockIdx.x * 256 + threadIdx.x;
    if (i < BNc) g_dinv[i] = rsqrtf(g_deg[i]);
}

// ---------------------------------------------------------------------------
// 3) scatter: node_feats = segment_mean of gated rows.
//    Block = (batch b, 64-column chunk). 64 threads; each thread owns one
//    column -> the 128x64 smem accumulator needs NO atomics, and all smem
//    stays under the 48KB static limit (no cudaFuncSetAttribute required).
// ---------------------------------------------------------------------------
__global__ void scatter_kernel(const float* __restrict__ lh,
                               const int* __restrict__ submap) {
    __shared__ float accs[Nc][64];                // 32 KB
    __shared__ float sg[Sc];
    __shared__ int   sn[Sc];
    __shared__ float sinv[Nc];
    int b = blockIdx.x;
    int cb = blockIdx.y * 64;
    int tid = threadIdx.x;                        // 0..63, owns one column

    for (int i = tid; i < Sc; i += 64) {
        sg[i] = g_gate[b * Sc + i];
        sn[i] = submap[b * Sc + i];
    }
    for (int i = tid; i < Nc; i += 64)
        sinv[i] = 1.f / fmaxf(g_cnt[b * Nc + i], 1.f);
    for (int i = tid; i < Nc * 64; i += 64) ((float*)accs)[i] = 0.f;
    __syncthreads();

    const float* base = lh + (size_t)b * Sc * Hc + cb;
#pragma unroll 4
    for (int s = 0; s < Sc; ++s) {
        float v = __ldg(base + (size_t)s * Hc + tid);
        accs[sn[s]][tid] += v * sg[s];
    }
    __syncthreads();

    float* od = g_nodef + (size_t)b * Nc * Hc + cb;
    for (int n = 0; n < Nc; ++n)
        od[(size_t)n * Hc + tid] = accs[n][tid] * sinv[n];
}

// ---------------------------------------------------------------------------
// 4) GEMM: C[8192 x 128] = act(A[8192 x K]) @ B[K x 128]
//    64x128 block tile, 4x8 thread tile, K-tile 32.
//    SRC: 0 -> A = g_nodef (layer 1, no activation)
//         1 -> A = g_acc   (layer 2, relu(a + abias) fused on the load)
//    C is always g_h.
// ---------------------------------------------------------------------------
template <int K, int SRC>
__global__ __launch_bounds__(256)
void gemm_kernel(const float* __restrict__ abias,
                 const float* __restrict__ Bm) {
    const float* __restrict__ A = (SRC == 0) ? g_nodef : g_acc;
    float* __restrict__ C = g_h;
    __shared__ float As[32][68];    // transposed, padded (68%4==0 -> f4 aligned)
    __shared__ float Bs[32][128];
    int tid = threadIdx.x;
    int tx = tid & 15, ty = tid >> 4;
    int rowBase = blockIdx.x * 64;

    float acc[4][8];
#pragma unroll
    for (int i = 0; i < 4; ++i)
#pragma unroll
        for (int j = 0; j < 8; ++j) acc[i][j] = 0.f;

    for (int k0 = 0; k0 < K; k0 += 32) {
#pragma unroll
        for (int t = 0; t < 2; ++t) {                      // A: 64x32 = 512 f4
            int idx = tid + t * 256;
            int r = idx >> 3, q = idx & 7;
            float4 av = *(const float4*)&A[(size_t)(rowBase + r) * K + k0 + (q << 2)];
            if (SRC == 1) {
                av.x = fmaxf(av.x + abias[k0 + (q << 2) + 0], 0.f);
                av.y = fmaxf(av.y + abias[k0 + (q << 2) + 1], 0.f);
                av.z = fmaxf(av.z + abias[k0 + (q << 2) + 2], 0.f);
                av.w = fmaxf(av.w + abias[k0 + (q << 2) + 3], 0.f);
            }
            As[(q << 2) + 0][r] = av.x;
            As[(q << 2) + 1][r] = av.y;
            As[(q << 2) + 2][r] = av.z;
            As[(q << 2) + 3][r] = av.w;
        }
#pragma unroll
        for (int t = 0; t < 4; ++t) {                      // B: 32x128 = 1024 f4
            int idx = tid + t * 256;
            int kb = idx >> 5, c4 = idx & 31;
            float4 bv = *(const float4*)&Bm[(size_t)(k0 + kb) * 128 + (c4 << 2)];
            *(float4*)&Bs[kb][c4 << 2] = bv;
        }
        __syncthreads();
#pragma unroll
        for (int kk = 0; kk < 32; ++kk) {
            float4 a  = *(const float4*)&As[kk][ty << 2];
            float4 b0 = *(const float4*)&Bs[kk][tx << 3];
            float4 b1 = *(const float4*)&Bs[kk][(tx << 3) + 4];
            float av[4] = {a.x, a.y, a.z, a.w};
            float bv[8] = {b0.x, b0.y, b0.z, b0.w, b1.x, b1.y, b1.z, b1.w};
#pragma unroll
            for (int i = 0; i < 4; ++i)
#pragma unroll
                for (int j = 0; j < 8; ++j) acc[i][j] += av[i] * bv[j];
        }
        __syncthreads();
    }
#pragma unroll
    for (int i = 0; i < 4; ++i) {
        size_t row = rowBase + (ty << 2) + i;
        float4 v0 = make_float4(acc[i][0], acc[i][1], acc[i][2], acc[i][3]);
        float4 v1 = make_float4(acc[i][4], acc[i][5], acc[i][6], acc[i][7]);
        *(float4*)&C[row * 128 + (tx << 3)] = v0;
        *(float4*)&C[row * 128 + (tx << 3) + 4] = v1;
    }
}

// ---------------------------------------------------------------------------
// 5) message passing: acc = h*dinv^2 (self loop) then edge atomics
// ---------------------------------------------------------------------------
__global__ void msg_init_kernel() {
    int i = blockIdx.x * 256 + threadIdx.x;   // over BN*GH
    int nd = i >> 7;
    float dv = g_dinv[nd];
    g_acc[i] = g_h[i] * dv * dv;
}

__global__ void msg_edge_kernel(const int* __restrict__ eidx) {
    int wid = (blockIdx.x * blockDim.x + threadIdx.x) >> 5;  // edge id
    int lane = threadIdx.x & 31;
    int b = wid >> 10, le = wid & (Ec - 1);
    int src = eidx[b * 2 * Ec + le];
    int dst = eidx[b * 2 * Ec + Ec + le];
    int gs = b * Nc + src, gd = b * Nc + dst;
    float nrm = g_dinv[gs] * g_dinv[gd];
    float4 hv = ((const float4*)g_h)[gs * 32 + lane];
    float* o = g_acc + (size_t)gd * GHc + lane * 4;
    atomicAdd(o + 0, hv.x * nrm);
    atomicAdd(o + 1, hv.y * nrm);
    atomicAdd(o + 2, hv.z * nrm);
    atomicAdd(o + 3, hv.w * nrm);
}

// ---------------------------------------------------------------------------
// 6) pooled[b,d] = mean_n relu(acc[b,n,d] + b2[d])
// ---------------------------------------------------------------------------
__global__ void pool_kernel(const float* __restrict__ b2) {
    int b = blockIdx.x, d = threadIdx.x;
    float bias = b2[d];
    float sum = 0.f;
    for (int n = 0; n < Nc; ++n)
        sum += fmaxf(g_acc[((size_t)b * Nc + n) * GHc + d] + bias, 0.f);
    g_pool[b * GHc + d] = sum * (1.f / Nc);
}

// ---------------------------------------------------------------------------
// 7) head: out[b,:] = relu(concat(cls, pooled) @ Wf1 + bf1) @ Wf2 + bf2
// ---------------------------------------------------------------------------
__global__ void fc_kernel(const float* __restrict__ lh,
                          const float* __restrict__ Wf1,
                          const float* __restrict__ bf1,
                          const float* __restrict__ Wf2,
                          const float* __restrict__ bf2,
                          float* __restrict__ out) {
    __shared__ float sin_[Hc + GHc];       // 896
    __shared__ float red[4][FHc];
    __shared__ float rr[2][8];
    int b = blockIdx.x, tid = threadIdx.x;

    for (int i = tid; i < Hc + GHc; i += 256)
        sin_[i] = (i < Hc) ? lh[(size_t)b * Sc * Hc + i] : g_pool[b * GHc + i - Hc];
    __syncthreads();

    int jg = (tid & 63) << 2, ks = tid >> 6;
    float a0 = 0.f, a1 = 0.f, a2 = 0.f, a3 = 0.f;
    for (int k = ks; k < Hc + GHc; k += 4) {
        float s = sin_[k];
        float4 w = *(const float4*)&Wf1[(size_t)k * FHc + jg];
        a0 += s * w.x; a1 += s * w.y; a2 += s * w.z; a3 += s * w.w;
    }
    red[ks][jg + 0] = a0; red[ks][jg + 1] = a1;
    red[ks][jg + 2] = a2; red[ks][jg + 3] = a3;
    __syncthreads();

    int j = tid;
    float h = bf1[j] + red[0][j] + red[1][j] + red[2][j] + red[3][j];
    h = fmaxf(h, 0.f);
    float p0 = h * Wf2[2 * j], p1 = h * Wf2[2 * j + 1];
#pragma unroll
    for (int o = 16; o; o >>= 1) {
        p0 += __shfl_xor_sync(0xffffffffu, p0, o);
        p1 += __shfl_xor_sync(0xffffffffu, p1, o);
    }
    if ((tid & 31) == 0) { rr[0][tid >> 5] = p0; rr[1][tid >> 5] = p1; }
    __syncthreads();
    if (tid == 0) {
        float t0 = 0.f, t1 = 0.f;
        for (int w = 0; w < 8; ++w) { t0 += rr[0][w]; t1 += rr[1][w]; }
        out[b * 2 + 0] = t0 + bf2[0];
        out[b * 2 + 1] = t1 + bf2[1];
    }
}

// ---------------------------------------------------------------------------
extern "C" void kernel_launch(void* const* d_in, const int* in_sizes, int n_in,
                              void* d_out, int out_size) {
    const float* lh     = (const float*)d_in[0];
    const int*   submap = (const int*)d_in[1];
    const int*   eidx   = (const int*)d_in[2];
    // d_in[3] = num_nodes (constant 128)
    const float* wr  = (const float*)d_in[4];
    const float* br  = (const float*)d_in[5];
    const float* W1  = (const float*)d_in[6];
    const float* b1  = (const float*)d_in[7];
    const float* W2  = (const float*)d_in[8];
    const float* b2  = (const float*)d_in[9];
    const float* Wf1 = (const float*)d_in[10];
    const float* bf1 = (const float*)d_in[11];
    const float* Wf2 = (const float*)d_in[12];
    const float* bf2 = (const float*)d_in[13];
    float* out = (float*)d_out;

    (void)in_sizes; (void)n_in; (void)out_size;

    gate_kernel<<<BSc / 8, 256>>>(lh, wr, br);
    init_kernel<<<BNc / 256, 256>>>();
    cntdeg_kernel<<<(BSc + NEc) / 256, 256>>>(submap, eidx);
    dinv_kernel<<<BNc / 256, 256>>>();
    scatter_kernel<<<dim3(Bc, Hc / 64), 64>>>(lh, submap);

    // layer 1: g_h = g_nodef @ W1
    gemm_kernel<Hc, 0><<<BNc / 64, 256>>>(b1, W1);
    msg_init_kernel<<<BNc * GHc / 256, 256>>>();
    msg_edge_kernel<<<NEc / 8, 256>>>(eidx);

    // layer 2: g_h = relu(g_acc + b1) @ W2  (activation fused into A load)
    gemm_kernel<GHc, 1><<<BNc / 64, 256>>>(b1, W2);
    msg_init_kernel<<<BNc * GHc / 256, 256>>>();
    msg_edge_kernel<<<NEc / 8, 256>>>(eidx);

    pool_kernel<<<Bc, GHc>>>(b2);
    fc_kernel<<<Bc, 256>>>(lh, Wf1, bf1, Wf2, bf2, out);
}

// round 4
// speedup vs baseline: 1.2575x; 1.2575x over previous
#include <cuda_runtime.h>
#include <cuda_bf16.h>
#include <math.h>

// Problem constants (fixed shapes)
constexpr int Bc = 64;    // batch
constexpr int Sc = 512;   // seq
constexpr int Hc = 768;   // hidden
constexpr int Nc = 128;   // nodes
constexpr int Ec = 1024;  // edges per batch
constexpr int GHc = 128;  // gcn hidden
constexpr int FHc = 256;  // fc hidden
constexpr int BNc = Bc * Nc;   // 8192
constexpr int BSc = Bc * Sc;   // 32768
constexpr int NEc = Bc * Ec;   // 65536

// Scratch (device globals — no allocation allowed)
__device__ float g_cnt[BNc];
__device__ float g_deg[BNc];
__device__ float g_dinv[BNc];
__device__ int   g_tok_off[BNc];
__device__ int   g_edge_off[BNc];
__device__ int   g_tokfill[BNc];
__device__ int   g_edgefill[BNc];
__device__ int   g_toklist[BSc];
__device__ int   g_elist[NEc];
__device__ __align__(16) float g_nodef[(size_t)BNc * Hc];   // 24 MiB
__device__ __align__(16) float g_h[(size_t)BNc * GHc];      // 4 MiB
__device__ __align__(16) float g_acc[(size_t)BNc * GHc];    // 4 MiB
__device__ __align__(16) float g_pool[Bc * GHc];

// ---------------------------------------------------------------------------
// 1) init: counts = 0, deg = 1 (self loop), fill cursors = 0
// ---------------------------------------------------------------------------
__global__ void init_kernel() {
    int i = blockIdx.x * 256 + threadIdx.x;
    if (i < BNc) {
        g_cnt[i] = 0.f; g_deg[i] = 1.f;
        g_tokfill[i] = 0; g_edgefill[i] = 0;
    }
}

// ---------------------------------------------------------------------------
// 2) histogram: token counts per node, in-degree per node
// ---------------------------------------------------------------------------
__global__ void cntdeg_kernel(const int* __restrict__ submap,
                              const int* __restrict__ eidx) {
    int i = blockIdx.x * 256 + threadIdx.x;
    if (i < BSc) {
        int b = i >> 9;                              // /512
        atomicAdd(&g_cnt[b * Nc + submap[i]], 1.f);
    } else {
        int e = i - BSc;
        if (e < NEc) {
            int b = e >> 10;                         // /1024
            int le = e & (Ec - 1);
            int dst = eidx[b * 2 * Ec + Ec + le];
            atomicAdd(&g_deg[b * Nc + dst], 1.f);
        }
    }
}

__global__ void dinv_kernel() {
    int i = blockIdx.x * 256 + threadIdx.x;
    if (i < BNc) g_dinv[i] = rsqrtf(g_deg[i]);
}

// ---------------------------------------------------------------------------
// 3) exclusive scan (8192 entries), blockIdx 0 -> token offs, 1 -> edge offs
// ---------------------------------------------------------------------------
__global__ void scan_kernel() {
    __shared__ int sm[1024];
    int arr = blockIdx.x;
    int t = threadIdx.x;
    int base = t * 8;
    int v[8];
    int s = 0;
#pragma unroll
    for (int i = 0; i < 8; ++i) {
        int c = (arr == 0) ? (int)g_cnt[base + i] : ((int)g_deg[base + i]) - 1;
        v[i] = s; s += c;
    }
    sm[t] = s;
    __syncthreads();
    for (int off = 1; off < 1024; off <<= 1) {
        int x = (t >= off) ? sm[t - off] : 0;
        __syncthreads();
        sm[t] += x;
        __syncthreads();
    }
    int excl = sm[t] - s;
    int* out = (arr == 0) ? g_tok_off : g_edge_off;
#pragma unroll
    for (int i = 0; i < 8; ++i) out[base + i] = excl + v[i];
}

// ---------------------------------------------------------------------------
// 4) CSR fill: token lists and incoming-edge source lists
// ---------------------------------------------------------------------------
__global__ void fill_kernel(const int* __restrict__ submap,
                            const int* __restrict__ eidx) {
    int i = blockIdx.x * 256 + threadIdx.x;
    if (i < BSc) {
        int b = i >> 9;
        int seg = b * Nc + submap[i];
        int pos = atomicAdd(&g_tokfill[seg], 1);
        g_toklist[g_tok_off[seg] + pos] = i;          // flat token index
    } else {
        int e = i - BSc;
        if (e < NEc) {
            int b = e >> 10;
            int le = e & (Ec - 1);
            int src = eidx[b * 2 * Ec + le];
            int dst = eidx[b * 2 * Ec + Ec + le];
            int segd = b * Nc + dst;
            int pos = atomicAdd(&g_edgefill[segd], 1);
            g_elist[g_edge_off[segd] + pos] = b * Nc + src;  // global src node
        }
    }
}

// ---------------------------------------------------------------------------
// 5) node features (fused gate + segment mean), gather form.
//    One block per node, 256 threads; thread owns cols {tid, tid+256, tid+512}.
//    For each of its tokens: full-row dot with wr (block reduce) -> sigmoid
//    gate, then accumulate v*gate in registers. One pass over last_hidden.
// ---------------------------------------------------------------------------
__global__ __launch_bounds__(256)
void node_feat_kernel(const float* __restrict__ lh,
                      const float* __restrict__ wr,
                      const float* __restrict__ brp) {
    __shared__ int toks[Sc];
    __shared__ float wsum[8];
    __shared__ float gbc;
    int node = blockIdx.x;
    int tid = threadIdx.x;
    int lane = tid & 31, wid = tid >> 5;

    int ntok = (int)g_cnt[node];
    int off = g_tok_off[node];
    for (int i = tid; i < ntok; i += 256) toks[i] = g_toklist[off + i];
    __syncthreads();

    float w0 = wr[tid], w1 = wr[tid + 256], w2 = wr[tid + 512];
    float br = brp[0];
    float a0 = 0.f, a1 = 0.f, a2 = 0.f;

    for (int j = 0; j < ntok; ++j) {
        const float* row = lh + (size_t)toks[j] * Hc;
        float v0 = row[tid], v1 = row[tid + 256], v2 = row[tid + 512];
        float p = v0 * w0 + v1 * w1 + v2 * w2;
#pragma unroll
        for (int o = 16; o; o >>= 1) p += __shfl_xor_sync(0xffffffffu, p, o);
        if (lane == 0) wsum[wid] = p;
        __syncthreads();
        if (tid == 0) {
            float s = wsum[0] + wsum[1] + wsum[2] + wsum[3]
                    + wsum[4] + wsum[5] + wsum[6] + wsum[7];
            gbc = 1.f / (1.f + expf(-(s + br)));
        }
        __syncthreads();
        float gate = gbc;
        a0 += v0 * gate; a1 += v1 * gate; a2 += v2 * gate;
    }

    float cinv = 1.f / fmaxf((float)ntok, 1.f);
    float* od = g_nodef + (size_t)node * Hc;
    od[tid]       = a0 * cinv;
    od[tid + 256] = a1 * cinv;
    od[tid + 512] = a2 * cinv;
}

// ---------------------------------------------------------------------------
// 6) GEMM: C[8192 x 128] = act(A[8192 x K]) @ B[K x 128]
//    64x128 block tile, 4x8 thread tile, K-tile 32.
//    SRC: 0 -> A = g_nodef (layer 1, no activation)
//         1 -> A = g_acc   (layer 2, relu(a + abias) fused on the load)
// ---------------------------------------------------------------------------
template <int K, int SRC>
__global__ __launch_bounds__(256)
void gemm_kernel(const float* __restrict__ abias,
                 const float* __restrict__ Bm) {
    const float* __restrict__ A = (SRC == 0) ? g_nodef : g_acc;
    float* __restrict__ C = g_h;
    __shared__ float As[32][68];
    __shared__ float Bs[32][128];
    int tid = threadIdx.x;
    int tx = tid & 15, ty = tid >> 4;
    int rowBase = blockIdx.x * 64;

    float acc[4][8];
#pragma unroll
    for (int i = 0; i < 4; ++i)
#pragma unroll
        for (int j = 0; j < 8; ++j) acc[i][j] = 0.f;

    for (int k0 = 0; k0 < K; k0 += 32) {
#pragma unroll
        for (int t = 0; t < 2; ++t) {                      // A: 64x32 = 512 f4
            int idx = tid + t * 256;
            int r = idx >> 3, q = idx & 7;
            float4 av = *(const float4*)&A[(size_t)(rowBase + r) * K + k0 + (q << 2)];
            if (SRC == 1) {
                av.x = fmaxf(av.x + abias[k0 + (q << 2) + 0], 0.f);
                av.y = fmaxf(av.y + abias[k0 + (q << 2) + 1], 0.f);
                av.z = fmaxf(av.z + abias[k0 + (q << 2) + 2], 0.f);
                av.w = fmaxf(av.w + abias[k0 + (q << 2) + 3], 0.f);
            }
            As[(q << 2) + 0][r] = av.x;
            As[(q << 2) + 1][r] = av.y;
            As[(q << 2) + 2][r] = av.z;
            As[(q << 2) + 3][r] = av.w;
        }
#pragma unroll
        for (int t = 0; t < 4; ++t) {                      // B: 32x128 = 1024 f4
            int idx = tid + t * 256;
            int kb = idx >> 5, c4 = idx & 31;
            float4 bv = *(const float4*)&Bm[(size_t)(k0 + kb) * 128 + (c4 << 2)];
            *(float4*)&Bs[kb][c4 << 2] = bv;
        }
        __syncthreads();
#pragma unroll
        for (int kk = 0; kk < 32; ++kk) {
            float4 a  = *(const float4*)&As[kk][ty << 2];
            float4 b0 = *(const float4*)&Bs[kk][tx << 3];
            float4 b1 = *(const float4*)&Bs[kk][(tx << 3) + 4];
            float av[4] = {a.x, a.y, a.z, a.w};
            float bv[8] = {b0.x, b0.y, b0.z, b0.w, b1.x, b1.y, b1.z, b1.w};
#pragma unroll
            for (int i = 0; i < 4; ++i)
#pragma unroll
                for (int j = 0; j < 8; ++j) acc[i][j] += av[i] * bv[j];
        }
        __syncthreads();
    }
#pragma unroll
    for (int i = 0; i < 4; ++i) {
        size_t row = rowBase + (ty << 2) + i;
        float4 v0 = make_float4(acc[i][0], acc[i][1], acc[i][2], acc[i][3]);
        float4 v1 = make_float4(acc[i][4], acc[i][5], acc[i][6], acc[i][7]);
        *(float4*)&C[row * 128 + (tx << 3)] = v0;
        *(float4*)&C[row * 128 + (tx << 3) + 4] = v1;
    }
}

// ---------------------------------------------------------------------------
// 7) message passing, gather form. One block (128 threads) per node; thread
//    owns one feature dim. Self loop + incoming edges, no atomics.
// ---------------------------------------------------------------------------
__global__ __launch_bounds__(128)
void msg_gather_kernel() {
    __shared__ int ssrc[128];
    int node = blockIdx.x;
    int tid = threadIdx.x;
    int nd = ((int)g_deg[node]) - 1;
    int off = g_edge_off[node];
    float di = g_dinv[node];
    float acc = g_h[(size_t)node * GHc + tid] * di * di;

    for (int c0 = 0; c0 < nd; c0 += 128) {
        int m = min(128, nd - c0);
        __syncthreads();
        if (tid < m) ssrc[tid] = g_elist[off + c0 + tid];
        __syncthreads();
        int j = 0;
        for (; j + 4 <= m; j += 4) {
            int s0 = ssrc[j], s1 = ssrc[j+1], s2 = ssrc[j+2], s3 = ssrc[j+3];
            float h0 = g_h[(size_t)s0 * GHc + tid];
            float h1 = g_h[(size_t)s1 * GHc + tid];
            float h2 = g_h[(size_t)s2 * GHc + tid];
            float h3 = g_h[(size_t)s3 * GHc + tid];
            acc += h0 * (g_dinv[s0] * di) + h1 * (g_dinv[s1] * di)
                 + h2 * (g_dinv[s2] * di) + h3 * (g_dinv[s3] * di);
        }
        for (; j < m; ++j) {
            int s0 = ssrc[j];
            acc += g_h[(size_t)s0 * GHc + tid] * (g_dinv[s0] * di);
        }
    }
    g_acc[(size_t)node * GHc + tid] = acc;
}

// ---------------------------------------------------------------------------
// 8) pooled[b,d] = mean_n relu(acc[b,n,d] + b2[d])
// ---------------------------------------------------------------------------
__global__ void pool_kernel(const float* __restrict__ b2) {
    int b = blockIdx.x, d = threadIdx.x;
    float bias = b2[d];
    float sum = 0.f;
    for (int n = 0; n < Nc; ++n)
        sum += fmaxf(g_acc[((size_t)b * Nc + n) * GHc + d] + bias, 0.f);
    g_pool[b * GHc + d] = sum * (1.f / Nc);
}

// ---------------------------------------------------------------------------
// 9) head: out[b,:] = relu(concat(cls, pooled) @ Wf1 + bf1) @ Wf2 + bf2
// ---------------------------------------------------------------------------
__global__ void fc_kernel(const float* __restrict__ lh,
                          const float* __restrict__ Wf1,
                          const float* __restrict__ bf1,
                          const float* __restrict__ Wf2,
                          const float* __restrict__ bf2,
                          float* __restrict__ out) {
    __shared__ float sin_[Hc + GHc];       // 896
    __shared__ float red[4][FHc];
    __shared__ float rr[2][8];
    int b = blockIdx.x, tid = threadIdx.x;

    for (int i = tid; i < Hc + GHc; i += 256)
        sin_[i] = (i < Hc) ? lh[(size_t)b * Sc * Hc + i] : g_pool[b * GHc + i - Hc];
    __syncthreads();

    int jg = (tid & 63) << 2, ks = tid >> 6;
    float a0 = 0.f, a1 = 0.f, a2 = 0.f, a3 = 0.f;
    for (int k = ks; k < Hc + GHc; k += 4) {
        float s = sin_[k];
        float4 w = *(const float4*)&Wf1[(size_t)k * FHc + jg];
        a0 += s * w.x; a1 += s * w.y; a2 += s * w.z; a3 += s * w.w;
    }
    red[ks][jg + 0] = a0; red[ks][jg + 1] = a1;
    red[ks][jg + 2] = a2; red[ks][jg + 3] = a3;
    __syncthreads();

    int j = tid;
    float h = bf1[j] + red[0][j] + red[1][j] + red[2][j] + red[3][j];
    h = fmaxf(h, 0.f);
    float p0 = h * Wf2[2 * j], p1 = h * Wf2[2 * j + 1];
#pragma unroll
    for (int o = 16; o; o >>= 1) {
        p0 += __shfl_xor_sync(0xffffffffu, p0, o);
        p1 += __shfl_xor_sync(0xffffffffu, p1, o);
    }
    if ((tid & 31) == 0) { rr[0][tid >> 5] = p0; rr[1][tid >> 5] = p1; }
    __syncthreads();
    if (tid == 0) {
        float t0 = 0.f, t1 = 0.f;
        for (int w = 0; w < 8; ++w) { t0 += rr[0][w]; t1 += rr[1][w]; }
        out[b * 2 + 0] = t0 + bf2[0];
        out[b * 2 + 1] = t1 + bf2[1];
    }
}

// ---------------------------------------------------------------------------
extern "C" void kernel_launch(void* const* d_in, const int* in_sizes, int n_in,
                              void* d_out, int out_size) {
    const float* lh     = (const float*)d_in[0];
    const int*   submap = (const int*)d_in[1];
    const int*   eidx   = (const int*)d_in[2];
    // d_in[3] = num_nodes (constant 128)
    const float* wr  = (const float*)d_in[4];
    const float* br  = (const float*)d_in[5];
    const float* W1  = (const float*)d_in[6];
    const float* b1  = (const float*)d_in[7];
    const float* W2  = (const float*)d_in[8];
    const float* b2  = (const float*)d_in[9];
    const float* Wf1 = (const float*)d_in[10];
    const float* bf1 = (const float*)d_in[11];
    const float* Wf2 = (const float*)d_in[12];
    const float* bf2 = (const float*)d_in[13];
    float* out = (float*)d_out;

    (void)in_sizes; (void)n_in; (void)out_size;

    init_kernel<<<BNc / 256, 256>>>();
    cntdeg_kernel<<<(BSc + NEc) / 256, 256>>>(submap, eidx);
    scan_kernel<<<2, 1024>>>();
    dinv_kernel<<<BNc / 256, 256>>>();
    fill_kernel<<<(BSc + NEc) / 256, 256>>>(submap, eidx);

    node_feat_kernel<<<BNc, 256>>>(lh, wr, br);

    // layer 1: g_h = g_nodef @ W1 ; g_acc = propagate(g_h)
    gemm_kernel<Hc, 0><<<BNc / 64, 256>>>(b1, W1);
    msg_gather_kernel<<<BNc, 128>>>();

    // layer 2: g_h = relu(g_acc + b1) @ W2 ; g_acc = propagate(g_h)
    gemm_kernel<GHc, 1><<<BNc / 64, 256>>>(b1, W2);
    msg_gather_kernel<<<BNc, 128>>>();

    pool_kernel<<<Bc, GHc>>>(b2);
    fc_kernel<<<Bc, 256>>>(lh, Wf1, bf1, Wf2, bf2, out);
}

// round 7
// speedup vs baseline: 1.3833x; 1.1001x over previous
#include <cuda_runtime.h>
#include <cuda_bf16.h>
#include <math.h>

// Problem constants (fixed shapes)
constexpr int Bc = 64;    // batch
constexpr int Sc = 512;   // seq
constexpr int Hc = 768;   // hidden
constexpr int Nc = 128;   // nodes
constexpr int Ec = 1024;  // edges per batch
constexpr int GHc = 128;  // gcn hidden
constexpr int FHc = 256;  // fc hidden
constexpr int BNc = Bc * Nc;   // 8192
constexpr int BSc = Bc * Sc;   // 32768
constexpr int NEc = Bc * Ec;   // 65536

// Scratch (device globals — no allocation allowed)
__device__ int   g_ntok[BNc];
__device__ int   g_indeg[BNc];
__device__ float g_dinv[BNc];
__device__ int   g_tok_off[BNc];
__device__ int   g_edge_off[BNc];
__device__ int   g_toklist[BSc];
__device__ int   g_elist[NEc];
__device__ __align__(16) float g_nodef[(size_t)BNc * Hc];   // 24 MiB
__device__ __align__(16) float g_h[(size_t)BNc * GHc];      // 4 MiB
__device__ __align__(16) float g_acc[(size_t)BNc * GHc];    // 4 MiB

// ---------------------------------------------------------------------------
// 1) prep: per-batch CSR build in one kernel. Block = batch.
//    smem histograms -> in-block scan -> smem-cursor fill. No global sync.
// ---------------------------------------------------------------------------
__global__ __launch_bounds__(256)
void prep_kernel(const int* __restrict__ submap, const int* __restrict__ eidx) {
    __shared__ int scnt[Nc], sdeg[Nc];
    __shared__ int sscan[256];
    __shared__ int btok[Nc], bedg[Nc];
    __shared__ int sft[Nc], sfe[Nc];
    int b = blockIdx.x, tid = threadIdx.x;

    if (tid < Nc) { scnt[tid] = 0; sdeg[tid] = 0; sft[tid] = 0; sfe[tid] = 0; }
    __syncthreads();

    for (int i = tid; i < Sc; i += 256) atomicAdd(&scnt[submap[b * Sc + i]], 1);
    for (int e = tid; e < Ec; e += 256) atomicAdd(&sdeg[eidx[b * 2 * Ec + Ec + e]], 1);
    __syncthreads();

    // two 128-wide inclusive scans in parallel (tok in [0,128), edge in [128,256))
    int j = tid & 127;
    sscan[tid] = (tid < 128) ? scnt[j] : sdeg[j];
    __syncthreads();
    for (int off = 1; off < 128; off <<= 1) {
        int x = (j >= off) ? sscan[tid - off] : 0;
        __syncthreads();
        sscan[tid] += x;
        __syncthreads();
    }

    if (tid < Nc) {
        int n = tid;
        int ntok = scnt[n];
        int toff = b * Sc + sscan[n] - ntok;          // exclusive
        int ind  = sdeg[n];
        int eoff = b * Ec + sscan[128 + n] - ind;
        g_ntok[b * Nc + n] = ntok;
        g_tok_off[b * Nc + n] = toff;
        g_indeg[b * Nc + n] = ind;
        g_edge_off[b * Nc + n] = eoff;
        g_dinv[b * Nc + n] = rsqrtf(1.f + (float)ind);
        btok[n] = toff; bedg[n] = eoff;
    }
    __syncthreads();

    for (int i = tid; i < Sc; i += 256) {
        int n = submap[b * Sc + i];
        int pos = atomicAdd(&sft[n], 1);
        g_toklist[btok[n] + pos] = b * Sc + i;
    }
    for (int e = tid; e < Ec; e += 256) {
        int src = eidx[b * 2 * Ec + e];
        int dst = eidx[b * 2 * Ec + Ec + e];
        int pos = atomicAdd(&sfe[dst], 1);
        g_elist[bedg[dst] + pos] = b * Nc + src;
    }
}

// ---------------------------------------------------------------------------
// 2) node features (fused gate + segment mean), gather form, two-phase.
//    Block = node, 256 threads. Phase A: warp-per-token gate dot (parallel).
//    Phase B: register accumulation; row re-reads hit L1.
// ---------------------------------------------------------------------------
__global__ __launch_bounds__(256)
void node_feat_kernel(const float* __restrict__ lh,
                      const float* __restrict__ wr,
                      const float* __restrict__ brp) {
    __shared__ int   toks[Sc];
    __shared__ float sgate[Sc];
    int node = blockIdx.x;
    int tid = threadIdx.x;
    int lane = tid & 31, wid = tid >> 5;

    int ntok = g_ntok[node];
    int off = g_tok_off[node];
    for (int i = tid; i < ntok; i += 256) toks[i] = g_toklist[off + i];
    __syncthreads();

    float br = brp[0];
    const float4* w4 = (const float4*)wr;
    for (int t = wid; t < ntok; t += 8) {
        const float4* r4 = (const float4*)(lh + (size_t)toks[t] * Hc);
        float p = 0.f;
#pragma unroll
        for (int jj = 0; jj < 6; ++jj) {
            float4 a = r4[lane + jj * 32];
            float4 w = __ldg(&w4[lane + jj * 32]);
            p += a.x * w.x + a.y * w.y + a.z * w.z + a.w * w.w;
        }
#pragma unroll
        for (int o = 16; o; o >>= 1) p += __shfl_xor_sync(0xffffffffu, p, o);
        if (lane == 0) sgate[t] = 1.f / (1.f + expf(-(p + br)));
    }
    __syncthreads();

    float a0 = 0.f, a1 = 0.f, a2 = 0.f;
    for (int t = 0; t < ntok; ++t) {
        const float* row = lh + (size_t)toks[t] * Hc;
        float g = sgate[t];
        a0 += row[tid] * g;
        a1 += row[tid + 256] * g;
        a2 += row[tid + 512] * g;
    }

    float cinv = 1.f / fmaxf((float)ntok, 1.f);
    float* od = g_nodef + (size_t)node * Hc;
    od[tid]       = a0 * cinv;
    od[tid + 256] = a1 * cinv;
    od[tid + 512] = a2 * cinv;
}

// ---------------------------------------------------------------------------
// 3) GEMM: C[8192 x 128] = act(A[8192 x K]) @ B[K x 128]
//    32x128 block tile, 128 threads, 4x8 thread tile, K-tile 32.
//    256 CTAs -> all co-resident on 148 SMs (no wave quantization).
//    SRC: 0 -> A = g_nodef; 1 -> A = g_acc with relu(a + abias) fused.
// ---------------------------------------------------------------------------
template <int K, int SRC>
__global__ __launch_bounds__(128)
void gemm_kernel(const float* __restrict__ abias,
                 const float* __restrict__ Bm) {
    const float* __restrict__ A = (SRC == 0) ? g_nodef : g_acc;
    float* __restrict__ C = g_h;
    __shared__ float As[32][33];   // transposed; pad 33 -> conflict-free
    __shared__ float Bs[32][128];
    int tid = threadIdx.x;
    int tx = tid & 15, ty = tid >> 4;    // tx: 16 col groups, ty: 8 row groups
    int rowBase = blockIdx.x * 32;

    float acc[4][8];
#pragma unroll
    for (int i = 0; i < 4; ++i)
#pragma unroll
        for (int j = 0; j < 8; ++j) acc[i][j] = 0.f;

    for (int k0 = 0; k0 < K; k0 += 32) {
#pragma unroll
        for (int t = 0; t < 2; ++t) {                      // A: 32x32 = 256 f4
            int idx = tid + t * 128;
            int r = idx >> 3, q = idx & 7;
            float4 av = *(const float4*)&A[(size_t)(rowBase + r) * K + k0 + (q << 2)];
            if (SRC == 1) {
                av.x = fmaxf(av.x + abias[k0 + (q << 2) + 0], 0.f);
                av.y = fmaxf(av.y + abias[k0 + (q << 2) + 1], 0.f);
                av.z = fmaxf(av.z + abias[k0 + (q << 2) + 2], 0.f);
                av.w = fmaxf(av.w + abias[k0 + (q << 2) + 3], 0.f);
            }
            As[(q << 2) + 0][r] = av.x;
            As[(q << 2) + 1][r] = av.y;
            As[(q << 2) + 2][r] = av.z;
            As[(q << 2) + 3][r] = av.w;
        }
#pragma unroll
        for (int t = 0; t < 8; ++t) {                      // B: 32x128 = 1024 f4
            int idx = tid + t * 128;
            int kb = idx >> 5, c4 = idx & 31;
            *(float4*)&Bs[kb][c4 << 2] =
                *(const float4*)&Bm[(size_t)(k0 + kb) * 128 + (c4 << 2)];
        }
        __syncthreads();
#pragma unroll
        for (int kk = 0; kk < 32; ++kk) {
            float av[4];
#pragma unroll
            for (int i = 0; i < 4; ++i) av[i] = As[kk][(ty << 2) + i];
            float4 b0 = *(const float4*)&Bs[kk][tx << 3];
            float4 b1 = *(const float4*)&Bs[kk][(tx << 3) + 4];
            float bv[8] = {b0.x, b0.y, b0.z, b0.w, b1.x, b1.y, b1.z, b1.w};
#pragma unroll
            for (int i = 0; i < 4; ++i)
#pragma unroll
                for (int j = 0; j < 8; ++j) acc[i][j] += av[i] * bv[j];
        }
        __syncthreads();
    }
#pragma unroll
    for (int i = 0; i < 4; ++i) {
        size_t row = rowBase + (ty << 2) + i;
        float4 v0 = make_float4(acc[i][0], acc[i][1], acc[i][2], acc[i][3]);
        float4 v1 = make_float4(acc[i][4], acc[i][5], acc[i][6], acc[i][7]);
        *(float4*)&C[row * 128 + (tx << 3)] = v0;
        *(float4*)&C[row * 128 + (tx << 3) + 4] = v1;
    }
}

// ---------------------------------------------------------------------------
// 4) message passing, gather form. Block (128 threads) per node; thread owns
//    one feature dim. Self loop + incoming edges, no atomics.
// ---------------------------------------------------------------------------
__global__ __launch_bounds__(128)
void msg_gather_kernel() {
    __shared__ int ssrc[128];
    int node = blockIdx.x;
    int tid = threadIdx.x;
    int nd = g_indeg[node];
    int off = g_edge_off[node];
    float di = g_dinv[node];
    float acc = g_h[(size_t)node * GHc + tid] * di * di;

    for (int c0 = 0; c0 < nd; c0 += 128) {
        int m = min(128, nd - c0);
        __syncthreads();
        if (tid < m) ssrc[tid] = g_elist[off + c0 + tid];
        __syncthreads();
        int j = 0;
        for (; j + 4 <= m; j += 4) {
            int s0 = ssrc[j], s1 = ssrc[j+1], s2 = ssrc[j+2], s3 = ssrc[j+3];
            float h0 = g_h[(size_t)s0 * GHc + tid];
            float h1 = g_h[(size_t)s1 * GHc + tid];
            float h2 = g_h[(size_t)s2 * GHc + tid];
            float h3 = g_h[(size_t)s3 * GHc + tid];
            acc += h0 * (g_dinv[s0] * di) + h1 * (g_dinv[s1] * di)
                 + h2 * (g_dinv[s2] * di) + h3 * (g_dinv[s3] * di);
        }
        for (; j < m; ++j) {
            int s0 = ssrc[j];
            acc += g_h[(size_t)s0 * GHc + tid] * (g_dinv[s0] * di);
        }
    }
    g_acc[(size_t)node * GHc + tid] = acc;
}

// ---------------------------------------------------------------------------
// 5) head (pool fused): pooled[b,:] = mean_n relu(acc[b,n,:] + b2);
//    out[b,:] = relu(concat(cls, pooled) @ Wf1 + bf1) @ Wf2 + bf2
// ---------------------------------------------------------------------------
__global__ __launch_bounds__(256)
void fc_kernel(const float* __restrict__ lh,
               const float* __restrict__ b2,
               const float* __restrict__ Wf1,
               const float* __restrict__ bf1,
               const float* __restrict__ Wf2,
               const float* __restrict__ bf2,
               float* __restrict__ out) {
    __shared__ float sin_[Hc + GHc];       // 896
    __shared__ float psum[GHc];
    __shared__ float red[4][FHc];
    __shared__ float rr[2][8];
    int b = blockIdx.x, tid = threadIdx.x;

    for (int i = tid; i < Hc; i += 256)
        sin_[i] = lh[(size_t)b * Sc * Hc + i];

    // pool: d = tid&127, half = tid>>7 handles 64 nodes
    {
        int d = tid & 127, half = tid >> 7;
        float bias = b2[d];
        float s = 0.f;
        const float* base = g_acc + ((size_t)(b * Nc + half * 64)) * GHc + d;
#pragma unroll 4
        for (int n = 0; n < 64; ++n)
            s += fmaxf(base[(size_t)n * GHc] + bias, 0.f);
        if (half == 1) psum[d] = s;
        __syncthreads();
        if (half == 0) sin_[Hc + d] = (s + psum[d]) * (1.f / Nc);
    }
    __syncthreads();

    int jg = (tid & 63) << 2, ks = tid >> 6;
    float a0 = 0.f, a1 = 0.f, a2 = 0.f, a3 = 0.f;
    for (int k = ks; k < Hc + GHc; k += 4) {
        float s = sin_[k];
        float4 w = *(const float4*)&Wf1[(size_t)k * FHc + jg];
        a0 += s * w.x; a1 += s * w.y; a2 += s * w.z; a3 += s * w.w;
    }
    red[ks][jg + 0] = a0; red[ks][jg + 1] = a1;
    red[ks][jg + 2] = a2; red[ks][jg + 3] = a3;
    __syncthreads();

    int j = tid;
    float h = bf1[j] + red[0][j] + red[1][j] + red[2][j] + red[3][j];
    h = fmaxf(h, 0.f);
    float p0 = h * Wf2[2 * j], p1 = h * Wf2[2 * j + 1];
#pragma unroll
    for (int o = 16; o; o >>= 1) {
        p0 += __shfl_xor_sync(0xffffffffu, p0, o);
        p1 += __shfl_xor_sync(0xffffffffu, p1, o);
    }
    if ((tid & 31) == 0) { rr[0][tid >> 5] = p0; rr[1][tid >> 5] = p1; }
    __syncthreads();
    if (tid == 0) {
        float t0 = 0.f, t1 = 0.f;
        for (int w = 0; w < 8; ++w) { t0 += rr[0][w]; t1 += rr[1][w]; }
        out[b * 2 + 0] = t0 + bf2[0];
        out[b * 2 + 1] = t1 + bf2[1];
    }
}

// ---------------------------------------------------------------------------
extern "C" void kernel_launch(void* const* d_in, const int* in_sizes, int n_in,
                              void* d_out, int out_size) {
    const float* lh     = (const float*)d_in[0];
    const int*   submap = (const int*)d_in[1];
    const int*   eidx   = (const int*)d_in[2];
    // d_in[3] = num_nodes (constant 128)
    const float* wr  = (const float*)d_in[4];
    const float* br  = (const float*)d_in[5];
    const float* W1  = (const float*)d_in[6];
    const float* b1  = (const float*)d_in[7];
    const float* W2  = (const float*)d_in[8];
    const float* b2  = (const float*)d_in[9];
    const float* Wf1 = (const float*)d_in[10];
    const float* bf1 = (const float*)d_in[11];
    const float* Wf2 = (const float*)d_in[12];
    const float* bf2 = (const float*)d_in[13];
    float* out = (float*)d_out;

    (void)in_sizes; (void)n_in; (void)out_size;

    prep_kernel<<<Bc, 256>>>(submap, eidx);
    node_feat_kernel<<<BNc, 256>>>(lh, wr, br);

    // layer 1: g_h = g_nodef @ W1 ; g_acc = propagate(g_h)
    gemm_kernel<Hc, 0><<<BNc / 32, 128>>>(b1, W1);
    msg_gather_kernel<<<BNc, 128>>>();

    // layer 2: g_h = relu(g_acc + b1) @ W2 ; g_acc = propagate(g_h)
    gemm_kernel<GHc, 1><<<BNc / 32, 128>>>(b1, W2);
    msg_gather_kernel<<<BNc, 128>>>();

    fc_kernel<<<Bc, 256>>>(lh, b2, Wf1, bf1, Wf2, bf2, out);
}